// round 2
// baseline (speedup 1.0000x reference)
#include <cuda_runtime.h>
#include <cuda_bf16.h>

#define N_NODES 4096
#define IN_DIM  256
#define HID_DIM 128
#define MLP_W   16
#define MAXNNZ  256

// Scratch (static device globals — no allocation)
__device__ int                g_col[N_NODES * MAXNNZ];
__device__ float              g_w[N_NODES * MAXNNZ];
__device__ int                g_nnz[N_NODES];
__device__ float              g_rs[N_NODES];
__device__ unsigned long long g_csfx[N_NODES];   // fixed-point (2^40) column sums
__device__ float              g_drow[N_NODES];
__device__ float              g_dcol[N_NODES];
__device__ float              g_diag[N_NODES];
__device__ float              g_hid[N_NODES * HID_DIM];

// ---------------------------------------------------------------------------
__global__ void init_kernel() {
    int i = blockIdx.x * blockDim.x + threadIdx.x;
    if (i < N_NODES) g_csfx[i] = 0ull;
}

// ---------------------------------------------------------------------------
// One block (256 thr) per row. Two-phase ballot scan of the dense adj row:
//   pass 1: ballot each 32-col chunk, stash masks in registers (lane-indexed),
//           per-warp nnz counts -> tiny 8-entry exclusive scan (2 barriers).
//   pass 2: nonzero lanes recompute position = warp_base + running +
//           popc(mask & lt), evaluate the closed-form edge gate, store CSR,
//           accumulate row sum (deterministic tree) and col sums (fixed-point
//           integer atomics => deterministic).
__global__ __launch_bounds__(256) void build_kernel(
    const float* __restrict__ adj,
    const float* __restrict__ xdeg,
    const float* __restrict__ ydeg,
    const float* __restrict__ We1,
    const float* __restrict__ be1,
    const float* __restrict__ We2,
    const float* __restrict__ be2)
{
    const int row  = blockIdx.x;
    const int t    = threadIdx.x;
    const int wid  = t >> 5;
    const int lane = t & 31;

    __shared__ float c0[MLP_W], c1[MLP_W], c2[MLP_W], cb[MLP_W], dd[MLP_W];
    __shared__ float sdb;
    __shared__ int   swcnt[8], swoff[8], stot;
    __shared__ float sgs[8];

    if (t < MLP_W) {
        c0[t] = We1[t];                 // We1[0][w]  (feat = adj value)
        c1[t] = We1[MLP_W + t];         // We1[1][w]  (feat = row degree)
        c2[t] = We1[2 * MLP_W + t];     // We1[2][w]  (feat = col degree)
        cb[t] = be1[t];
        dd[t] = We2[t * 2 + 1] - We2[t * 2 + 0];
    }
    if (t == 0) sdb = be2[1] - be2[0];

    const float* arow = adj + (long)row * N_NODES;

    // ---- pass 1: ballots + warp counts ----
    unsigned msave = 0u;     // lane s (s<16) holds the ballot mask of chunk s
    int wcnt = 0;
#pragma unroll
    for (int s = 0; s < 16; s++) {
        float v = arow[s * 256 + t];
        unsigned mask = __ballot_sync(0xffffffffu, v != 0.0f);
        if (lane == s) msave = mask;
        wcnt += __popc(mask);
    }
    if (lane == 0) swcnt[wid] = wcnt;
    __syncthreads();

    if (t < 8) {
        // tiny sequential exclusive scan (deterministic, 8 entries)
        int acc = 0;
        for (int i = 0; i < 8; i++) {
            if (i == t) swoff[t] = acc;
            acc += swcnt[i];
        }
        if (t == 0) stot = acc;
    }
    __syncthreads();

    const int wbase = swoff[wid];
    const float dr  = xdeg[(long)row * N_NODES];   // xdeg[row][0] == deg_row[row]

    // ---- pass 2: process nonzero lanes only (values re-read from L2) ----
    int   running = 0;
    float gs = 0.0f;
#pragma unroll
    for (int s = 0; s < 16; s++) {
        unsigned mask = __shfl_sync(0xffffffffu, msave, s);
        if (mask & (1u << lane)) {
            const int   j   = s * 256 + t;
            const float val = arow[j];
            const float dc  = ydeg[j];
            float l = 0.0f;
#pragma unroll
            for (int w = 0; w < MLP_W; w++) {
                float h = fmaf(val, c0[w], fmaf(dr, c1[w], fmaf(dc, c2[w], cb[w])));
                h = fmaxf(h, 0.0f);
                l = fmaf(h, dd[w], l);
            }
            l += sdb;
            // softmax(...)[1] == sigmoid(l1 - l0); edge weight = adj * gate
            const float wgt = val / (1.0f + __expf(-l));
            gs += wgt;
            const int pos = wbase + running + __popc(mask & ((1u << lane) - 1u));
            if (pos < MAXNNZ) {
                g_col[(long)row * MAXNNZ + pos] = j;
                g_w  [(long)row * MAXNNZ + pos] = wgt;
            }
            atomicAdd(&g_csfx[j],
                      (unsigned long long)(wgt * 1099511627776.0f)); // *2^40
        }
        running += __popc(mask);
    }

    // ---- deterministic row-sum reduction ----
#pragma unroll
    for (int off = 16; off > 0; off >>= 1)
        gs += __shfl_xor_sync(0xffffffffu, gs, off);
    if (lane == 0) sgs[wid] = gs;
    __syncthreads();
    if (t == 0) {
        float r = 0.0f;
        for (int i = 0; i < 8; i++) r += sgs[i];
        g_rs[row]  = 1.0f + r;                       // + self loop
        g_nnz[row] = (stot < MAXNNZ) ? stot : MAXNNZ;
    }
}

// ---------------------------------------------------------------------------
__global__ void norm_kernel(const float* __restrict__ resid_w) {
    int i = blockIdx.x * blockDim.x + threadIdx.x;
    if (i >= N_NODES) return;
    const float rs = g_rs[i];
    const float cs = 1.0f + (float)g_csfx[i] * 9.094947017729282e-13f; // *2^-40
    const float drow = (rs > 0.0f) ? rsqrtf(rs) : 0.0f;
    const float dcol = (cs > 0.0f) ? rsqrtf(cs) : 0.0f;
    g_drow[i] = drow;
    g_dcol[i] = dcol;
    g_diag[i] = drow * dcol + resid_w[0];   // (An diagonal self-loop) + residual
}

// ---------------------------------------------------------------------------
// Fused: out_row = An@x + rw*x  (row of 256), then hid_row = out_row@W1 + b1.
// Degree scaling (drow*dcol) folded into the smem weight load.
__global__ __launch_bounds__(128) void spmm1_kernel(
    const float* __restrict__ x,
    const float* __restrict__ W1,
    const float* __restrict__ b1)
{
    const int row = blockIdx.x;
    const int t   = threadIdx.x;   // 128 threads

    __shared__ int   sc[MAXNNZ];
    __shared__ float sw[MAXNNZ];
    __shared__ float so[IN_DIM];

    const int   nnz = g_nnz[row];
    const float dri = g_drow[row];
    for (int k = t; k < nnz; k += 128) {
        const int c = g_col[(long)row * MAXNNZ + k];
        sc[k] = c;
        sw[k] = g_w[(long)row * MAXNNZ + k] * dri * g_dcol[c];
    }
    __syncthreads();

    const float2* x2 = (const float2*)x;          // row c = x2 + c*128
    const float   dg = g_diag[row];
    float2 xr = x2[(long)row * 128 + t];
    float  a0 = dg * xr.x;
    float  a1 = dg * xr.y;
    for (int e = 0; e < nnz; e++) {
        const float  we = sw[e];
        const float2 v  = x2[(long)sc[e] * 128 + t];
        a0 = fmaf(we, v.x, a0);
        a1 = fmaf(we, v.y, a1);
    }
    so[2 * t]     = a0;
    so[2 * t + 1] = a1;
    __syncthreads();

    float h = b1[t];
    const float4* so4 = (const float4*)so;
#pragma unroll 8
    for (int kk = 0; kk < IN_DIM / 4; kk++) {
        const float4 s4 = so4[kk];
        h = fmaf(s4.x, W1[(4 * kk + 0) * HID_DIM + t], h);
        h = fmaf(s4.y, W1[(4 * kk + 1) * HID_DIM + t], h);
        h = fmaf(s4.z, W1[(4 * kk + 2) * HID_DIM + t], h);
        h = fmaf(s4.w, W1[(4 * kk + 3) * HID_DIM + t], h);
    }
    g_hid[(long)row * HID_DIM + t] = h;
}

// ---------------------------------------------------------------------------
// Fused: out2_row = An@hid + rw*hid (row of 128), then out2_row@W2 + b2.
__global__ __launch_bounds__(128) void spmm2_kernel(
    const float* __restrict__ W2,
    const float* __restrict__ b2,
    float* __restrict__ out)
{
    const int row = blockIdx.x;
    const int t   = threadIdx.x;   // 128 threads

    __shared__ int   sc[MAXNNZ];
    __shared__ float sw[MAXNNZ];
    __shared__ float r0[128], r1[128];

    const int   nnz = g_nnz[row];
    const float dri = g_drow[row];
    for (int k = t; k < nnz; k += 128) {
        const int c = g_col[(long)row * MAXNNZ + k];
        sc[k] = c;
        sw[k] = g_w[(long)row * MAXNNZ + k] * dri * g_dcol[c];
    }
    __syncthreads();

    float acc = g_diag[row] * g_hid[(long)row * HID_DIM + t];
    for (int e = 0; e < nnz; e++)
        acc = fmaf(sw[e], g_hid[(long)sc[e] * HID_DIM + t], acc);

    r0[t] = acc * W2[t * 2 + 0];
    r1[t] = acc * W2[t * 2 + 1];
    __syncthreads();
    for (int off = 64; off > 0; off >>= 1) {
        if (t < off) { r0[t] += r0[t + off]; r1[t] += r1[t + off]; }
        __syncthreads();
    }
    if (t == 0) {
        out[row * 2 + 0] = r0[0] + b2[0];
        out[row * 2 + 1] = r1[0] + b2[1];
    }
}

// ---------------------------------------------------------------------------
extern "C" void kernel_launch(void* const* d_in, const int* in_sizes, int n_in,
                              void* d_out, int out_size)
{
    const float* x    = (const float*)d_in[0];
    const float* adj  = (const float*)d_in[1];
    const float* xdeg = (const float*)d_in[2];
    const float* ydeg = (const float*)d_in[3];
    const float* We1  = (const float*)d_in[4];
    const float* be1  = (const float*)d_in[5];
    const float* We2  = (const float*)d_in[6];
    const float* be2  = (const float*)d_in[7];
    const float* W1   = (const float*)d_in[8];
    const float* b1   = (const float*)d_in[9];
    const float* W2   = (const float*)d_in[10];
    const float* b2   = (const float*)d_in[11];
    const float* rw   = (const float*)d_in[12];
    float* out        = (float*)d_out;

    init_kernel <<<16, 256>>>();
    build_kernel<<<N_NODES, 256>>>(adj, xdeg, ydeg, We1, be1, We2, be2);
    norm_kernel <<<16, 256>>>(rw);
    spmm1_kernel<<<N_NODES, 128>>>(x, W1, b1);
    spmm2_kernel<<<N_NODES, 128>>>(W2, b2, out);
}

// round 3
// speedup vs baseline: 1.1603x; 1.1603x over previous
#include <cuda_runtime.h>
#include <cuda_bf16.h>

#define N_NODES 4096
#define IN_DIM  256
#define HID_DIM 128
#define MLP_W   16
#define MAXNNZ  256

// Scratch (static device globals — no allocation)
__device__ int                g_col[N_NODES * MAXNNZ];
__device__ float              g_w[N_NODES * MAXNNZ];
__device__ int                g_nnz[N_NODES];
__device__ float              g_rs[N_NODES];
__device__ unsigned long long g_csfx[N_NODES];   // fixed-point (2^40) column sums
__device__ float              g_drow[N_NODES];
__device__ float              g_dcol[N_NODES];
__device__ float              g_diag[N_NODES];
__device__ float              g_P  [N_NODES * HID_DIM];   // x @ W1
__device__ float              g_hid[N_NODES * HID_DIM];   // An@P + rw*P + b1
__device__ float              g_z  [N_NODES * 2];         // hid @ W2

// ---------------------------------------------------------------------------
__global__ void init_kernel() {
    int i = blockIdx.x * blockDim.x + threadIdx.x;
    if (i < N_NODES) g_csfx[i] = 0ull;
}

// ---------------------------------------------------------------------------
// One block (256 thr) per row. Ballot-scan of the dense adj row, closed-form
// edge gate, CSR build, deterministic row sums (fixed tree) and column sums
// (fixed-point integer atomics).
__global__ __launch_bounds__(256) void build_kernel(
    const float* __restrict__ adj,
    const float* __restrict__ xdeg,
    const float* __restrict__ ydeg,
    const float* __restrict__ We1,
    const float* __restrict__ be1,
    const float* __restrict__ We2,
    const float* __restrict__ be2)
{
    const int row  = blockIdx.x;
    const int t    = threadIdx.x;
    const int wid  = t >> 5;
    const int lane = t & 31;

    __shared__ float c0[MLP_W], c1[MLP_W], c2[MLP_W], cb[MLP_W], dd[MLP_W];
    __shared__ float sdb;
    __shared__ int   swcnt[8], swoff[8], stot;
    __shared__ float sgs[8];

    if (t < MLP_W) {
        c0[t] = We1[t];                 // We1[0][w]  (feat = adj value)
        c1[t] = We1[MLP_W + t];         // We1[1][w]  (feat = row degree)
        c2[t] = We1[2 * MLP_W + t];     // We1[2][w]  (feat = col degree)
        cb[t] = be1[t];
        dd[t] = We2[t * 2 + 1] - We2[t * 2 + 0];
    }
    if (t == 0) sdb = be2[1] - be2[0];

    const float* arow = adj + (long)row * N_NODES;

    // ---- pass 1: ballots + warp counts ----
    unsigned msave = 0u;     // lane s (s<16) holds the ballot mask of chunk s
    int wcnt = 0;
#pragma unroll
    for (int s = 0; s < 16; s++) {
        float v = arow[s * 256 + t];
        unsigned mask = __ballot_sync(0xffffffffu, v != 0.0f);
        if (lane == s) msave = mask;
        wcnt += __popc(mask);
    }
    if (lane == 0) swcnt[wid] = wcnt;
    __syncthreads();

    if (t < 8) {
        int acc = 0;
        for (int i = 0; i < 8; i++) {
            if (i == t) swoff[t] = acc;
            acc += swcnt[i];
        }
        if (t == 0) stot = acc;
    }
    __syncthreads();

    const int wbase = swoff[wid];
    const float dr  = xdeg[(long)row * N_NODES];   // xdeg[row][0] == deg_row[row]

    // ---- pass 2: process nonzero lanes only (values re-read from L2) ----
    int   running = 0;
    float gs = 0.0f;
#pragma unroll
    for (int s = 0; s < 16; s++) {
        unsigned mask = __shfl_sync(0xffffffffu, msave, s);
        if (mask & (1u << lane)) {
            const int   j   = s * 256 + t;
            const float val = arow[j];
            const float dc  = ydeg[j];
            float l = 0.0f;
#pragma unroll
            for (int w = 0; w < MLP_W; w++) {
                float h = fmaf(val, c0[w], fmaf(dr, c1[w], fmaf(dc, c2[w], cb[w])));
                h = fmaxf(h, 0.0f);
                l = fmaf(h, dd[w], l);
            }
            l += sdb;
            // softmax(...)[1] == sigmoid(l1 - l0); edge weight = adj * gate
            const float wgt = val / (1.0f + __expf(-l));
            gs += wgt;
            const int pos = wbase + running + __popc(mask & ((1u << lane) - 1u));
            if (pos < MAXNNZ) {
                g_col[(long)row * MAXNNZ + pos] = j;
                g_w  [(long)row * MAXNNZ + pos] = wgt;
            }
            atomicAdd(&g_csfx[j],
                      (unsigned long long)(wgt * 1099511627776.0f)); // *2^40
        }
        running += __popc(mask);
    }

    // ---- deterministic row-sum reduction ----
#pragma unroll
    for (int off = 16; off > 0; off >>= 1)
        gs += __shfl_xor_sync(0xffffffffu, gs, off);
    if (lane == 0) sgs[wid] = gs;
    __syncthreads();
    if (t == 0) {
        float r = 0.0f;
        for (int i = 0; i < 8; i++) r += sgs[i];
        g_rs[row]  = 1.0f + r;                       // + self loop
        g_nnz[row] = (stot < MAXNNZ) ? stot : MAXNNZ;
    }
}

// ---------------------------------------------------------------------------
__global__ void norm_kernel(const float* __restrict__ resid_w) {
    int i = blockIdx.x * blockDim.x + threadIdx.x;
    if (i >= N_NODES) return;
    const float rs = g_rs[i];
    const float cs = 1.0f + (float)g_csfx[i] * 9.094947017729282e-13f; // *2^-40
    const float drow = (rs > 0.0f) ? rsqrtf(rs) : 0.0f;
    const float dcol = (cs > 0.0f) ? rsqrtf(cs) : 0.0f;
    g_drow[i] = drow;
    g_dcol[i] = dcol;
    g_diag[i] = drow * dcol + resid_w[0];   // (An diagonal self-loop) + residual
}

// ---------------------------------------------------------------------------
// Tiled dense GEMM: P = x @ W1.  (An@x)@W1 == An@(x@W1), so do the GEMM once
// and gather on 128-wide rows instead of 256-wide.
// BM=32 rows, BN=128 (full), BK=32. 256 threads, 4x4 register tile each.
__global__ __launch_bounds__(256) void gemm1_kernel(
    const float* __restrict__ x,
    const float* __restrict__ W1)
{
    __shared__ float sx[32][32];       // [r][k]
    __shared__ float sw[32][HID_DIM];  // [k][c]

    const int t    = threadIdx.x;
    const int row0 = blockIdx.x * 32;
    const int tx   = t & 31;           // col group: cols tx*4 .. tx*4+3
    const int ty   = t >> 5;           // row group: rows ty*4 .. ty*4+3

    float acc[4][4] = {};

    for (int kt = 0; kt < IN_DIM; kt += 32) {
        // x tile: thread -> (r = t/8, k4 = (t%8)*4)
        {
            const int r  = t >> 3;
            const int k4 = (t & 7) * 4;
            const float4 v = *(const float4*)&x[(long)(row0 + r) * IN_DIM + kt + k4];
            sx[r][k4]     = v.x; sx[r][k4 + 1] = v.y;
            sx[r][k4 + 2] = v.z; sx[r][k4 + 3] = v.w;
        }
        // W1 tile: 4 float4 per thread
        {
            const int kk = t >> 5;
            const int c4 = (t & 31) * 4;
#pragma unroll
            for (int q = 0; q < 4; q++) {
                const int k = kk + q * 8;
                *(float4*)&sw[k][c4] =
                    *(const float4*)&W1[(long)(kt + k) * HID_DIM + c4];
            }
        }
        __syncthreads();

#pragma unroll
        for (int k = 0; k < 32; k++) {
            const float4 wv = *(const float4*)&sw[k][tx * 4];
            const float a0 = sx[ty * 4 + 0][k];
            const float a1 = sx[ty * 4 + 1][k];
            const float a2 = sx[ty * 4 + 2][k];
            const float a3 = sx[ty * 4 + 3][k];
            acc[0][0] = fmaf(a0, wv.x, acc[0][0]);
            acc[0][1] = fmaf(a0, wv.y, acc[0][1]);
            acc[0][2] = fmaf(a0, wv.z, acc[0][2]);
            acc[0][3] = fmaf(a0, wv.w, acc[0][3]);
            acc[1][0] = fmaf(a1, wv.x, acc[1][0]);
            acc[1][1] = fmaf(a1, wv.y, acc[1][1]);
            acc[1][2] = fmaf(a1, wv.z, acc[1][2]);
            acc[1][3] = fmaf(a1, wv.w, acc[1][3]);
            acc[2][0] = fmaf(a2, wv.x, acc[2][0]);
            acc[2][1] = fmaf(a2, wv.y, acc[2][1]);
            acc[2][2] = fmaf(a2, wv.z, acc[2][2]);
            acc[2][3] = fmaf(a2, wv.w, acc[2][3]);
            acc[3][0] = fmaf(a3, wv.x, acc[3][0]);
            acc[3][1] = fmaf(a3, wv.y, acc[3][1]);
            acc[3][2] = fmaf(a3, wv.z, acc[3][2]);
            acc[3][3] = fmaf(a3, wv.w, acc[3][3]);
        }
        __syncthreads();
    }

#pragma unroll
    for (int j = 0; j < 4; j++) {
        float4 v = make_float4(acc[j][0], acc[j][1], acc[j][2], acc[j][3]);
        *(float4*)&g_P[(long)(row0 + ty * 4 + j) * HID_DIM + tx * 4] = v;
    }
}

// ---------------------------------------------------------------------------
// agg1: hid = An@P + rw*P + b1. One block (128 thr) per row; 4 B/thread/edge.
__global__ __launch_bounds__(128) void agg1_kernel(const float* __restrict__ b1)
{
    const int row = blockIdx.x;
    const int t   = threadIdx.x;

    __shared__ int   sc[MAXNNZ];
    __shared__ float sw[MAXNNZ];

    const int   nnz = g_nnz[row];
    const float dri = g_drow[row];
    for (int k = t; k < nnz; k += 128) {
        const int c = g_col[(long)row * MAXNNZ + k];
        sc[k] = c;
        sw[k] = g_w[(long)row * MAXNNZ + k] * dri * g_dcol[c];
    }
    __syncthreads();

    float acc = fmaf(g_diag[row], g_P[(long)row * HID_DIM + t], b1[t]);
    for (int e = 0; e < nnz; e++)
        acc = fmaf(sw[e], g_P[(long)sc[e] * HID_DIM + t], acc);
    g_hid[(long)row * HID_DIM + t] = acc;
}

// ---------------------------------------------------------------------------
// z = hid @ W2 (4096x128 @ 128x2). One block (128 thr) per row, block reduce.
__global__ __launch_bounds__(128) void z_kernel(const float* __restrict__ W2)
{
    const int row = blockIdx.x;
    const int t   = threadIdx.x;
    __shared__ float s0[4], s1[4];

    const float v  = g_hid[(long)row * HID_DIM + t];
    float r0 = v * W2[t * 2 + 0];
    float r1 = v * W2[t * 2 + 1];
#pragma unroll
    for (int off = 16; off > 0; off >>= 1) {
        r0 += __shfl_xor_sync(0xffffffffu, r0, off);
        r1 += __shfl_xor_sync(0xffffffffu, r1, off);
    }
    if ((t & 31) == 0) { s0[t >> 5] = r0; s1[t >> 5] = r1; }
    __syncthreads();
    if (t == 0)
        g_z[row * 2 + 0] = s0[0] + s0[1] + s0[2] + s0[3];
    else if (t == 1)
        g_z[row * 2 + 1] = s1[0] + s1[1] + s1[2] + s1[3];
}

// ---------------------------------------------------------------------------
// out = An@z + rw*z + b2. One warp per row, 8 rows per block.
__global__ __launch_bounds__(256) void agg2_kernel(
    const float* __restrict__ b2,
    float* __restrict__ out)
{
    const int row  = blockIdx.x * 8 + (threadIdx.x >> 5);
    const int lane = threadIdx.x & 31;

    const int   nnz = g_nnz[row];
    const float dri = g_drow[row];
    float a0 = 0.0f, a1 = 0.0f;
    for (int e = lane; e < nnz; e += 32) {
        const int   c = g_col[(long)row * MAXNNZ + e];
        const float w = g_w[(long)row * MAXNNZ + e] * dri * g_dcol[c];
        a0 = fmaf(w, g_z[c * 2 + 0], a0);
        a1 = fmaf(w, g_z[c * 2 + 1], a1);
    }
#pragma unroll
    for (int off = 16; off > 0; off >>= 1) {
        a0 += __shfl_xor_sync(0xffffffffu, a0, off);
        a1 += __shfl_xor_sync(0xffffffffu, a1, off);
    }
    if (lane == 0) {
        const float dg = g_diag[row];
        out[row * 2 + 0] = a0 + dg * g_z[row * 2 + 0] + b2[0];
        out[row * 2 + 1] = a1 + dg * g_z[row * 2 + 1] + b2[1];
    }
}

// ---------------------------------------------------------------------------
extern "C" void kernel_launch(void* const* d_in, const int* in_sizes, int n_in,
                              void* d_out, int out_size)
{
    const float* x    = (const float*)d_in[0];
    const float* adj  = (const float*)d_in[1];
    const float* xdeg = (const float*)d_in[2];
    const float* ydeg = (const float*)d_in[3];
    const float* We1  = (const float*)d_in[4];
    const float* be1  = (const float*)d_in[5];
    const float* We2  = (const float*)d_in[6];
    const float* be2  = (const float*)d_in[7];
    const float* W1   = (const float*)d_in[8];
    const float* b1   = (const float*)d_in[9];
    const float* W2   = (const float*)d_in[10];
    const float* b2   = (const float*)d_in[11];
    const float* rw   = (const float*)d_in[12];
    float* out        = (float*)d_out;

    init_kernel <<<16, 256>>>();
    gemm1_kernel<<<N_NODES / 32, 256>>>(x, W1);   // independent of build
    build_kernel<<<N_NODES, 256>>>(adj, xdeg, ydeg, We1, be1, We2, be2);
    norm_kernel <<<16, 256>>>(rw);
    agg1_kernel <<<N_NODES, 128>>>(b1);
    z_kernel    <<<N_NODES, 128>>>(W2);
    agg2_kernel <<<N_NODES / 8, 256>>>(b2, out);
}

// round 4
// speedup vs baseline: 1.5025x; 1.2950x over previous
#include <cuda_runtime.h>
#include <cuda_bf16.h>

#define N_NODES 4096
#define IN_DIM  256
#define HID_DIM 128
#define MLP_W   16
#define MAXNNZ  256

// Scratch (static device globals — no allocation)
__device__ int                g_col[N_NODES * MAXNNZ];
__device__ float              g_w[N_NODES * MAXNNZ];
__device__ int                g_nnz[N_NODES];
__device__ float              g_rs[N_NODES];
__device__ unsigned long long g_csfx[N_NODES];   // fixed-point (2^40) column sums
__device__ float              g_P  [N_NODES * HID_DIM];   // x @ W1
__device__ float              g_z  [N_NODES * 2];         // (An@x@W1+rw*x@W1+b1) @ W2

#define FX_TO_F 9.094947017729282e-13f   /* 2^-40 */

// ---------------------------------------------------------------------------
// Tiled dense GEMM: P = x @ W1  ((An@x)@W1 == An@(x@W1)).
// BM=32, BN=128, BK=32; 256 threads, 4x4 register tile.
// First 16 blocks also zero g_csfx (init fused; runs before build on stream).
__global__ __launch_bounds__(256) void gemm1_kernel(
    const float* __restrict__ x,
    const float* __restrict__ W1)
{
    __shared__ float sx[32][32];       // [r][k]
    __shared__ float sw[32][HID_DIM];  // [k][c]

    const int t    = threadIdx.x;
    const int row0 = blockIdx.x * 32;
    const int tx   = t & 31;
    const int ty   = t >> 5;

    if (blockIdx.x < 16) g_csfx[blockIdx.x * 256 + t] = 0ull;

    float acc[4][4] = {};

    for (int kt = 0; kt < IN_DIM; kt += 32) {
        {
            const int r  = t >> 3;
            const int k4 = (t & 7) * 4;
            const float4 v = *(const float4*)&x[(long)(row0 + r) * IN_DIM + kt + k4];
            sx[r][k4]     = v.x; sx[r][k4 + 1] = v.y;
            sx[r][k4 + 2] = v.z; sx[r][k4 + 3] = v.w;
        }
        {
            const int kk = t >> 5;
            const int c4 = (t & 31) * 4;
#pragma unroll
            for (int q = 0; q < 4; q++) {
                const int k = kk + q * 8;
                *(float4*)&sw[k][c4] =
                    *(const float4*)&W1[(long)(kt + k) * HID_DIM + c4];
            }
        }
        __syncthreads();

#pragma unroll
        for (int k = 0; k < 32; k++) {
            const float4 wv = *(const float4*)&sw[k][tx * 4];
            const float a0 = sx[ty * 4 + 0][k];
            const float a1 = sx[ty * 4 + 1][k];
            const float a2 = sx[ty * 4 + 2][k];
            const float a3 = sx[ty * 4 + 3][k];
            acc[0][0] = fmaf(a0, wv.x, acc[0][0]);
            acc[0][1] = fmaf(a0, wv.y, acc[0][1]);
            acc[0][2] = fmaf(a0, wv.z, acc[0][2]);
            acc[0][3] = fmaf(a0, wv.w, acc[0][3]);
            acc[1][0] = fmaf(a1, wv.x, acc[1][0]);
            acc[1][1] = fmaf(a1, wv.y, acc[1][1]);
            acc[1][2] = fmaf(a1, wv.z, acc[1][2]);
            acc[1][3] = fmaf(a1, wv.w, acc[1][3]);
            acc[2][0] = fmaf(a2, wv.x, acc[2][0]);
            acc[2][1] = fmaf(a2, wv.y, acc[2][1]);
            acc[2][2] = fmaf(a2, wv.z, acc[2][2]);
            acc[2][3] = fmaf(a2, wv.w, acc[2][3]);
            acc[3][0] = fmaf(a3, wv.x, acc[3][0]);
            acc[3][1] = fmaf(a3, wv.y, acc[3][1]);
            acc[3][2] = fmaf(a3, wv.z, acc[3][2]);
            acc[3][3] = fmaf(a3, wv.w, acc[3][3]);
        }
        __syncthreads();
    }

#pragma unroll
    for (int j = 0; j < 4; j++) {
        float4 v = make_float4(acc[j][0], acc[j][1], acc[j][2], acc[j][3]);
        *(float4*)&g_P[(long)(row0 + ty * 4 + j) * HID_DIM + tx * 4] = v;
    }
}

// ---------------------------------------------------------------------------
// One block (256 thr) per row. All 16 row-chunk loads are batched into
// registers FIRST (MLP=16), then balloted; pass 2 reuses the register values
// (no adj re-read). Row-constant MLP term hoisted into smem.
__global__ __launch_bounds__(256) void build_kernel(
    const float* __restrict__ adj,
    const float* __restrict__ xdeg,
    const float* __restrict__ ydeg,
    const float* __restrict__ We1,
    const float* __restrict__ be1,
    const float* __restrict__ We2,
    const float* __restrict__ be2)
{
    const int row  = blockIdx.x;
    const int t    = threadIdx.x;
    const int wid  = t >> 5;
    const int lane = t & 31;

    __shared__ float c0[MLP_W], c2[MLP_W], dd[MLP_W], spre[MLP_W];
    __shared__ float sc1[MLP_W], scb[MLP_W];
    __shared__ float sdb;
    __shared__ int   swcnt[8], swoff[8], stot;
    __shared__ float sgs[8];

    if (t < MLP_W) {
        c0[t]  = We1[t];                 // We1[0][w]  (feat = adj value)
        sc1[t] = We1[MLP_W + t];         // We1[1][w]  (feat = row degree)
        c2[t]  = We1[2 * MLP_W + t];     // We1[2][w]  (feat = col degree)
        scb[t] = be1[t];
        dd[t]  = We2[t * 2 + 1] - We2[t * 2 + 0];
    }
    if (t == 0) sdb = be2[1] - be2[0];

    const float* arow = adj + (long)row * N_NODES;
    const float  dr   = xdeg[(long)row * N_NODES];   // deg_row[row]

    // ---- batched loads: 16 independent LDGs, full MLP ----
    float v[16];
#pragma unroll
    for (int s = 0; s < 16; s++) v[s] = arow[s * 256 + t];

    // ---- ballots + warp counts ----
    unsigned msave = 0u;     // lane s (s<16) holds the ballot mask of chunk s
    int wcnt = 0;
#pragma unroll
    for (int s = 0; s < 16; s++) {
        unsigned mask = __ballot_sync(0xffffffffu, v[s] != 0.0f);
        if (lane == s) msave = mask;
        wcnt += __popc(mask);
    }
    if (lane == 0) swcnt[wid] = wcnt;
    __syncthreads();

    if (t < MLP_W)   // row-constant MLP partial: dr*We1[1][w] + be1[w]
        spre[t] = fmaf(dr, sc1[t], scb[t]);
    if (t < 8) {
        int acc = 0;
        for (int i = 0; i < 8; i++) {
            if (i == t) swoff[t] = acc;
            acc += swcnt[i];
        }
        if (t == 0) stot = acc;
    }
    __syncthreads();

    const int wbase = swoff[wid];

    // ---- pass 2: gate MLP only on nonzero lanes ----
    int   running = 0;
    float gs = 0.0f;
#pragma unroll
    for (int s = 0; s < 16; s++) {
        unsigned mask = __shfl_sync(0xffffffffu, msave, s);
        if (mask & (1u << lane)) {
            const int   j   = s * 256 + t;
            const float val = v[s];
            const float dc  = ydeg[j];
            float l = 0.0f;
#pragma unroll
            for (int w = 0; w < MLP_W; w++) {
                float h = fmaf(val, c0[w], fmaf(dc, c2[w], spre[w]));
                h = fmaxf(h, 0.0f);
                l = fmaf(h, dd[w], l);
            }
            l += sdb;
            // softmax(...)[1] == sigmoid(l1 - l0); edge weight = adj * gate
            const float wgt = val / (1.0f + __expf(-l));
            gs += wgt;
            const int pos = wbase + running + __popc(mask & ((1u << lane) - 1u));
            if (pos < MAXNNZ) {
                g_col[(long)row * MAXNNZ + pos] = j;
                g_w  [(long)row * MAXNNZ + pos] = wgt;
            }
            atomicAdd(&g_csfx[j],
                      (unsigned long long)(wgt * 1099511627776.0f)); // *2^40
        }
        running += __popc(mask);
    }

    // ---- deterministic row-sum reduction ----
#pragma unroll
    for (int off = 16; off > 0; off >>= 1)
        gs += __shfl_xor_sync(0xffffffffu, gs, off);
    if (lane == 0) sgs[wid] = gs;
    __syncthreads();
    if (t == 0) {
        float r = 0.0f;
        for (int i = 0; i < 8; i++) r += sgs[i];
        g_rs[row]  = 1.0f + r;                       // + self loop
        g_nnz[row] = (stot < MAXNNZ) ? stot : MAXNNZ;
    }
}

// ---------------------------------------------------------------------------
// Fused: hid_row = An@P + rw*P + b1 (norm factors computed on the fly from
// g_rs/g_csfx), immediately reduced against W2 -> z_row. g_hid eliminated.
__global__ __launch_bounds__(128) void agg1z_kernel(
    const float* __restrict__ b1,
    const float* __restrict__ W2,
    const float* __restrict__ rw)
{
    const int row = blockIdx.x;
    const int t   = threadIdx.x;

    __shared__ int   sc[MAXNNZ];
    __shared__ float sw[MAXNNZ];
    __shared__ float s0[4], s1[4];

    const int   nnz = g_nnz[row];
    const float dri = rsqrtf(g_rs[row]);
    for (int k = t; k < nnz; k += 128) {
        const int c = g_col[(long)row * MAXNNZ + k];
        sc[k] = c;
        const float cs = 1.0f + (float)g_csfx[c] * FX_TO_F;
        sw[k] = g_w[(long)row * MAXNNZ + k] * dri * rsqrtf(cs);
    }
    __syncthreads();

    const float dcr  = rsqrtf(1.0f + (float)g_csfx[row] * FX_TO_F);
    const float diag = dri * dcr + rw[0];

    float acc = fmaf(diag, g_P[(long)row * HID_DIM + t], b1[t]);
    for (int e = 0; e < nnz; e++)
        acc = fmaf(sw[e], g_P[(long)sc[e] * HID_DIM + t], acc);

    // z_row = hid_row @ W2 (block reduce, deterministic tree)
    float r0 = acc * W2[t * 2 + 0];
    float r1 = acc * W2[t * 2 + 1];
#pragma unroll
    for (int off = 16; off > 0; off >>= 1) {
        r0 += __shfl_xor_sync(0xffffffffu, r0, off);
        r1 += __shfl_xor_sync(0xffffffffu, r1, off);
    }
    if ((t & 31) == 0) { s0[t >> 5] = r0; s1[t >> 5] = r1; }
    __syncthreads();
    if (t == 0)
        g_z[row * 2 + 0] = s0[0] + s0[1] + s0[2] + s0[3];
    else if (t == 1)
        g_z[row * 2 + 1] = s1[0] + s1[1] + s1[2] + s1[3];
}

// ---------------------------------------------------------------------------
// out = An@z + rw*z + b2. One warp per row, 8 rows per block.
__global__ __launch_bounds__(256) void agg2_kernel(
    const float* __restrict__ b2,
    const float* __restrict__ rw,
    float* __restrict__ out)
{
    const int row  = blockIdx.x * 8 + (threadIdx.x >> 5);
    const int lane = threadIdx.x & 31;

    const int   nnz = g_nnz[row];
    const float dri = rsqrtf(g_rs[row]);
    const float2* z2 = (const float2*)g_z;

    float a0 = 0.0f, a1 = 0.0f;
    for (int e = lane; e < nnz; e += 32) {
        const int   c  = g_col[(long)row * MAXNNZ + e];
        const float cs = 1.0f + (float)g_csfx[c] * FX_TO_F;
        const float w  = g_w[(long)row * MAXNNZ + e] * dri * rsqrtf(cs);
        const float2 z = z2[c];
        a0 = fmaf(w, z.x, a0);
        a1 = fmaf(w, z.y, a1);
    }
#pragma unroll
    for (int off = 16; off > 0; off >>= 1) {
        a0 += __shfl_xor_sync(0xffffffffu, a0, off);
        a1 += __shfl_xor_sync(0xffffffffu, a1, off);
    }
    if (lane == 0) {
        const float dcr  = rsqrtf(1.0f + (float)g_csfx[row] * FX_TO_F);
        const float diag = dri * dcr + rw[0];
        const float2 zr  = z2[row];
        out[row * 2 + 0] = a0 + diag * zr.x + b2[0];
        out[row * 2 + 1] = a1 + diag * zr.y + b2[1];
    }
}

// ---------------------------------------------------------------------------
extern "C" void kernel_launch(void* const* d_in, const int* in_sizes, int n_in,
                              void* d_out, int out_size)
{
    const float* x    = (const float*)d_in[0];
    const float* adj  = (const float*)d_in[1];
    const float* xdeg = (const float*)d_in[2];
    const float* ydeg = (const float*)d_in[3];
    const float* We1  = (const float*)d_in[4];
    const float* be1  = (const float*)d_in[5];
    const float* We2  = (const float*)d_in[6];
    const float* be2  = (const float*)d_in[7];
    const float* W1   = (const float*)d_in[8];
    const float* b1   = (const float*)d_in[9];
    const float* W2   = (const float*)d_in[10];
    const float* b2   = (const float*)d_in[11];
    const float* rw   = (const float*)d_in[12];
    float* out        = (float*)d_out;

    gemm1_kernel <<<N_NODES / 32, 256>>>(x, W1);   // also zeroes g_csfx
    build_kernel <<<N_NODES, 256>>>(adj, xdeg, ydeg, We1, be1, We2, be2);
    agg1z_kernel <<<N_NODES, 128>>>(b1, W2, rw);
    agg2_kernel  <<<N_NODES / 8, 256>>>(b2, rw, out);
}

// round 5
// speedup vs baseline: 1.5432x; 1.0271x over previous
#include <cuda_runtime.h>
#include <cuda_bf16.h>

#define N_NODES 4096
#define IN_DIM  256
#define HID_DIM 128
#define MLP_W   16
#define MAXNNZ  256

// Scratch (static device globals — no allocation)
__device__ int                g_col[N_NODES * MAXNNZ];
__device__ float              g_w[N_NODES * MAXNNZ];
__device__ int                g_nnz[N_NODES];
__device__ float              g_rs[N_NODES];
__device__ unsigned long long g_csfx[N_NODES];   // fixed-point (2^40) column sums
__device__ float              g_P  [N_NODES * HID_DIM];   // x @ W1
__device__ float              g_z  [N_NODES * 2];

#define FX_TO_F 9.094947017729282e-13f   /* 2^-40 */

// ---------------------------------------------------------------------------
// Tiled dense GEMM: P = x @ W1  ((An@x)@W1 == An@(x@W1)).
// BM=32, BN=128, BK=32; 256 threads, 4x4 register tile.
// First 16 blocks also zero g_csfx (init fused; runs before build on stream).
__global__ __launch_bounds__(256) void gemm1_kernel(
    const float* __restrict__ x,
    const float* __restrict__ W1)
{
    __shared__ float sx[32][32];       // [r][k]
    __shared__ float sw[32][HID_DIM];  // [k][c]

    const int t    = threadIdx.x;
    const int row0 = blockIdx.x * 32;
    const int tx   = t & 31;
    const int ty   = t >> 5;

    if (blockIdx.x < 16) g_csfx[blockIdx.x * 256 + t] = 0ull;

    float acc[4][4] = {};

    for (int kt = 0; kt < IN_DIM; kt += 32) {
        {
            const int r  = t >> 3;
            const int k4 = (t & 7) * 4;
            const float4 v = *(const float4*)&x[(long)(row0 + r) * IN_DIM + kt + k4];
            sx[r][k4]     = v.x; sx[r][k4 + 1] = v.y;
            sx[r][k4 + 2] = v.z; sx[r][k4 + 3] = v.w;
        }
        {
            const int kk = t >> 5;
            const int c4 = (t & 31) * 4;
#pragma unroll
            for (int q = 0; q < 4; q++) {
                const int k = kk + q * 8;
                *(float4*)&sw[k][c4] =
                    *(const float4*)&W1[(long)(kt + k) * HID_DIM + c4];
            }
        }
        __syncthreads();

#pragma unroll
        for (int k = 0; k < 32; k++) {
            const float4 wv = *(const float4*)&sw[k][tx * 4];
            const float a0 = sx[ty * 4 + 0][k];
            const float a1 = sx[ty * 4 + 1][k];
            const float a2 = sx[ty * 4 + 2][k];
            const float a3 = sx[ty * 4 + 3][k];
            acc[0][0] = fmaf(a0, wv.x, acc[0][0]);
            acc[0][1] = fmaf(a0, wv.y, acc[0][1]);
            acc[0][2] = fmaf(a0, wv.z, acc[0][2]);
            acc[0][3] = fmaf(a0, wv.w, acc[0][3]);
            acc[1][0] = fmaf(a1, wv.x, acc[1][0]);
            acc[1][1] = fmaf(a1, wv.y, acc[1][1]);
            acc[1][2] = fmaf(a1, wv.z, acc[1][2]);
            acc[1][3] = fmaf(a1, wv.w, acc[1][3]);
            acc[2][0] = fmaf(a2, wv.x, acc[2][0]);
            acc[2][1] = fmaf(a2, wv.y, acc[2][1]);
            acc[2][2] = fmaf(a2, wv.z, acc[2][2]);
            acc[2][3] = fmaf(a2, wv.w, acc[2][3]);
            acc[3][0] = fmaf(a3, wv.x, acc[3][0]);
            acc[3][1] = fmaf(a3, wv.y, acc[3][1]);
            acc[3][2] = fmaf(a3, wv.z, acc[3][2]);
            acc[3][3] = fmaf(a3, wv.w, acc[3][3]);
        }
        __syncthreads();
    }

#pragma unroll
    for (int j = 0; j < 4; j++) {
        float4 v = make_float4(acc[j][0], acc[j][1], acc[j][2], acc[j][3]);
        *(float4*)&g_P[(long)(row0 + ty * 4 + j) * HID_DIM + tx * 4] = v;
    }
}

// ---------------------------------------------------------------------------
// One block (256 thr) per row. 4 x LDG.128 per thread (front-batched), nibble
// masks + warp scans for deterministic CSR positions. Row-constant MLP term
// hoisted. Col sums via fixed-point atomics (deterministic).
__global__ __launch_bounds__(256) void build_kernel(
    const float* __restrict__ adj,
    const float* __restrict__ xdeg,
    const float* __restrict__ ydeg,
    const float* __restrict__ We1,
    const float* __restrict__ be1,
    const float* __restrict__ We2,
    const float* __restrict__ be2)
{
    const int row  = blockIdx.x;
    const int t    = threadIdx.x;
    const int wid  = t >> 5;
    const int lane = t & 31;

    __shared__ float c0[MLP_W], c2[MLP_W], dd[MLP_W], spre[MLP_W];
    __shared__ float sc1[MLP_W], scb[MLP_W];
    __shared__ float sdb;
    __shared__ int   swcnt[8], swoff[8], stot;
    __shared__ float sgs[8];

    if (t < MLP_W) {
        c0[t]  = We1[t];                 // We1[0][w]  (feat = adj value)
        sc1[t] = We1[MLP_W + t];         // We1[1][w]  (feat = row degree)
        c2[t]  = We1[2 * MLP_W + t];     // We1[2][w]  (feat = col degree)
        scb[t] = be1[t];
        dd[t]  = We2[t * 2 + 1] - We2[t * 2 + 0];
    }
    if (t == 0) sdb = be2[1] - be2[0];

    const float4* arow4 = (const float4*)(adj + (long)row * N_NODES);
    const float   dr    = xdeg[(long)row * N_NODES];   // deg_row[row]

    // ---- front-batched vector loads: 4 independent LDG.128 ----
    float4 v4[4];
#pragma unroll
    for (int s = 0; s < 4; s++) v4[s] = arow4[s * 256 + t];

    // ---- nibble nz masks + warp scans (register-only) ----
    int nib[4], lbase[4], wtot[4];
    int wcnt = 0;
#pragma unroll
    for (int s = 0; s < 4; s++) {
        const float4 v = v4[s];
        int nb = (v.x != 0.0f ? 1 : 0) | (v.y != 0.0f ? 2 : 0)
               | (v.z != 0.0f ? 4 : 0) | (v.w != 0.0f ? 8 : 0);
        nib[s] = nb;
        int cnt = __popc(nb);
        int pre = cnt;
#pragma unroll
        for (int off = 1; off < 32; off <<= 1) {
            int n = __shfl_up_sync(0xffffffffu, pre, off);
            if (lane >= off) pre += n;
        }
        lbase[s] = pre - cnt;                              // exclusive in-warp
        wtot[s]  = __shfl_sync(0xffffffffu, pre, 31);      // warp total
        wcnt    += wtot[s];
    }
    if (lane == 0) swcnt[wid] = wcnt;
    __syncthreads();

    if (t < MLP_W)   // row-constant MLP partial: dr*We1[1][w] + be1[w]
        spre[t] = fmaf(dr, sc1[t], scb[t]);
    if (t < 8) {
        int acc = 0;
        for (int i = 0; i < 8; i++) {
            if (i == t) swoff[t] = acc;
            acc += swcnt[i];
        }
        if (t == 0) stot = acc;
    }
    __syncthreads();

    const int wbase = swoff[wid];

    // ---- pass 2: gate MLP only on nonzero elements ----
    int   running = 0;
    float gs = 0.0f;
#pragma unroll
    for (int s = 0; s < 4; s++) {
        const int nb = nib[s];
        if (nb) {
            const float va[4] = { v4[s].x, v4[s].y, v4[s].z, v4[s].w };
            int rank = 0;
#pragma unroll
            for (int b = 0; b < 4; b++) {
                if (nb & (1 << b)) {
                    const int   j   = s * 1024 + t * 4 + b;
                    const float val = va[b];
                    const float dc  = ydeg[j];
                    float l = 0.0f;
#pragma unroll
                    for (int w = 0; w < MLP_W; w++) {
                        float h = fmaf(val, c0[w], fmaf(dc, c2[w], spre[w]));
                        h = fmaxf(h, 0.0f);
                        l = fmaf(h, dd[w], l);
                    }
                    l += sdb;
                    // softmax(...)[1] == sigmoid(l1-l0); weight = adj * gate
                    const float wgt = val / (1.0f + __expf(-l));
                    gs += wgt;
                    const int pos = wbase + running + lbase[s] + rank;
                    rank++;
                    if (pos < MAXNNZ) {
                        g_col[(long)row * MAXNNZ + pos] = j;
                        g_w  [(long)row * MAXNNZ + pos] = wgt;
                    }
                    atomicAdd(&g_csfx[j],
                              (unsigned long long)(wgt * 1099511627776.0f));
                }
            }
        }
        running += wtot[s];
    }

    // ---- deterministic row-sum reduction ----
#pragma unroll
    for (int off = 16; off > 0; off >>= 1)
        gs += __shfl_xor_sync(0xffffffffu, gs, off);
    if (lane == 0) sgs[wid] = gs;
    __syncthreads();
    if (t == 0) {
        float r = 0.0f;
        for (int i = 0; i < 8; i++) r += sgs[i];
        g_rs[row]  = 1.0f + r;                       // + self loop
        g_nnz[row] = (stot < MAXNNZ) ? stot : MAXNNZ;
    }
}

// ---------------------------------------------------------------------------
// Fused: hid_row = An@P + rw*P + b1, immediately reduced against W2 -> z_row.
// Also writes the final normalized edge weight back to g_w so agg2 can use
// it directly (no gather/rsqrt rework there).
__global__ __launch_bounds__(128) void agg1z_kernel(
    const float* __restrict__ b1,
    const float* __restrict__ W2,
    const float* __restrict__ rw)
{
    const int row = blockIdx.x;
    const int t   = threadIdx.x;

    __shared__ int   sc[MAXNNZ];
    __shared__ float sw[MAXNNZ];
    __shared__ float s0[4], s1[4];

    const int   nnz = g_nnz[row];
    const float dri = rsqrtf(g_rs[row]);
    for (int k = t; k < nnz; k += 128) {
        const int c = g_col[(long)row * MAXNNZ + k];
        sc[k] = c;
        const float cs = 1.0f + (float)g_csfx[c] * FX_TO_F;
        const float wf = g_w[(long)row * MAXNNZ + k] * dri * rsqrtf(cs);
        sw[k] = wf;
        g_w[(long)row * MAXNNZ + k] = wf;   // writeback for agg2
    }
    __syncthreads();

    const float dcr  = rsqrtf(1.0f + (float)g_csfx[row] * FX_TO_F);
    const float diag = dri * dcr + rw[0];

    float acc = fmaf(diag, g_P[(long)row * HID_DIM + t], b1[t]);
    for (int e = 0; e < nnz; e++)
        acc = fmaf(sw[e], g_P[(long)sc[e] * HID_DIM + t], acc);

    // z_row = hid_row @ W2 (deterministic reduction)
    float r0 = acc * W2[t * 2 + 0];
    float r1 = acc * W2[t * 2 + 1];
#pragma unroll
    for (int off = 16; off > 0; off >>= 1) {
        r0 += __shfl_xor_sync(0xffffffffu, r0, off);
        r1 += __shfl_xor_sync(0xffffffffu, r1, off);
    }
    if ((t & 31) == 0) { s0[t >> 5] = r0; s1[t >> 5] = r1; }
    __syncthreads();
    if (t == 0)
        g_z[row * 2 + 0] = s0[0] + s0[1] + s0[2] + s0[3];
    else if (t == 1)
        g_z[row * 2 + 1] = s1[0] + s1[1] + s1[2] + s1[3];
}

// ---------------------------------------------------------------------------
// out = An@z + rw*z + b2. One warp per row; weights pre-normalized by agg1z.
__global__ __launch_bounds__(256) void agg2_kernel(
    const float* __restrict__ b2,
    const float* __restrict__ rw,
    float* __restrict__ out)
{
    const int row  = blockIdx.x * 8 + (threadIdx.x >> 5);
    const int lane = threadIdx.x & 31;

    const int nnz = g_nnz[row];
    const float2* z2 = (const float2*)g_z;

    float a0 = 0.0f, a1 = 0.0f;
    for (int e = lane; e < nnz; e += 32) {
        const int   c = g_col[(long)row * MAXNNZ + e];
        const float w = g_w[(long)row * MAXNNZ + e];   // already normalized
        const float2 z = z2[c];
        a0 = fmaf(w, z.x, a0);
        a1 = fmaf(w, z.y, a1);
    }
#pragma unroll
    for (int off = 16; off > 0; off >>= 1) {
        a0 += __shfl_xor_sync(0xffffffffu, a0, off);
        a1 += __shfl_xor_sync(0xffffffffu, a1, off);
    }
    if (lane == 0) {
        const float dri  = rsqrtf(g_rs[row]);
        const float dcr  = rsqrtf(1.0f + (float)g_csfx[row] * FX_TO_F);
        const float diag = dri * dcr + rw[0];
        const float2 zr  = z2[row];
        out[row * 2 + 0] = a0 + diag * zr.x + b2[0];
        out[row * 2 + 1] = a1 + diag * zr.y + b2[1];
    }
}

// ---------------------------------------------------------------------------
extern "C" void kernel_launch(void* const* d_in, const int* in_sizes, int n_in,
                              void* d_out, int out_size)
{
    const float* x    = (const float*)d_in[0];
    const float* adj  = (const float*)d_in[1];
    const float* xdeg = (const float*)d_in[2];
    const float* ydeg = (const float*)d_in[3];
    const float* We1  = (const float*)d_in[4];
    const float* be1  = (const float*)d_in[5];
    const float* We2  = (const float*)d_in[6];
    const float* be2  = (const float*)d_in[7];
    const float* W1   = (const float*)d_in[8];
    const float* b1   = (const float*)d_in[9];
    const float* W2   = (const float*)d_in[10];
    const float* b2   = (const float*)d_in[11];
    const float* rw   = (const float*)d_in[12];
    float* out        = (float*)d_out;

    gemm1_kernel <<<N_NODES / 32, 256>>>(x, W1);   // also zeroes g_csfx
    build_kernel <<<N_NODES, 256>>>(adj, xdeg, ydeg, We1, be1, We2, be2);
    agg1z_kernel <<<N_NODES, 128>>>(b1, W2, rw);
    agg2_kernel  <<<N_NODES / 8, 256>>>(b2, rw, out);
}